// round 1
// baseline (speedup 1.0000x reference)
#include <cuda_runtime.h>
#include <cuda_bf16.h>
#include <cstdint>

// Skip-gram negative-sampling loss, fused:
//   loss = -(1/N) * sum_n [ logsig(dot(t_n, c_n)) + logsig(-dot(sum_k e_nk, t_n)) ]
//
// Inputs (metadata order):
//   d_in[0]: targets_1_pos          int32 [N]
//   d_in[1]: contexts_1_pos         int32 [N]
//   d_in[2]: contexts_0_pos_samples int32 [N, K]
//   d_in[3]: W_hidden               float32 [V, D]
//   d_in[4]: W_output               float32 [V, D]
// Output: float32 scalar.

#define D_DIM 128
#define K_NEG 5
#define NBLOCKS 2048
#define NTHREADS 256
#define WARPS_PER_BLOCK (NTHREADS / 32)

__device__ double g_acc;

__global__ void sg_init_kernel() { g_acc = 0.0; }

__device__ __forceinline__ float log_sigmoid(float x) {
    // stable: min(x,0) - log1p(exp(-|x|))
    return fminf(x, 0.0f) - log1pf(expf(-fabsf(x)));
}

__global__ __launch_bounds__(NTHREADS)
void sg_main_kernel(const int* __restrict__ tgt,
                    const int* __restrict__ ctx,
                    const int* __restrict__ neg,
                    const float4* __restrict__ Wh,   // [V, 32] float4 rows
                    const float4* __restrict__ Wo,   // [V, 32] float4 rows
                    long long n) {
    const int lane = threadIdx.x & 31;
    const int warp_in_block = threadIdx.x >> 5;
    const long long warp_global = (long long)blockIdx.x * WARPS_PER_BLOCK + warp_in_block;
    const long long warp_stride = (long long)gridDim.x * WARPS_PER_BLOCK;

    float local_sum = 0.0f;

    for (long long p = warp_global; p < n; p += warp_stride) {
        const size_t ti = (size_t)tgt[p];
        const size_t ci = (size_t)ctx[p];

        // each lane holds one float4 of the 128-float row
        const float4 t = Wh[ti * 32 + lane];
        const float4 c = Wo[ci * 32 + lane];

        float pos = t.x * c.x + t.y * c.y + t.z * c.z + t.w * c.w;

        // sum the K negative embeddings, then a single dot with t
        float4 s = make_float4(0.f, 0.f, 0.f, 0.f);
        const int* ng = neg + p * K_NEG;
#pragma unroll
        for (int k = 0; k < K_NEG; k++) {
            const float4 e = Wo[(size_t)ng[k] * 32 + lane];
            s.x += e.x; s.y += e.y; s.z += e.z; s.w += e.w;
        }
        float negdot = s.x * t.x + s.y * t.y + s.z * t.z + s.w * t.w;

        // warp reductions (butterfly -> all lanes hold the sum)
#pragma unroll
        for (int off = 16; off > 0; off >>= 1) {
            pos    += __shfl_xor_sync(0xFFFFFFFFu, pos, off);
            negdot += __shfl_xor_sync(0xFFFFFFFFu, negdot, off);
        }

        if (lane == 0) {
            local_sum += log_sigmoid(pos) + log_sigmoid(-negdot);
        }
    }

    // block reduce
    __shared__ float warp_sums[WARPS_PER_BLOCK];
    if (lane == 0) warp_sums[warp_in_block] = local_sum;
    __syncthreads();

    if (warp_in_block == 0) {
        float v = (lane < WARPS_PER_BLOCK) ? warp_sums[lane] : 0.0f;
#pragma unroll
        for (int off = 16; off > 0; off >>= 1)
            v += __shfl_xor_sync(0xFFFFFFFFu, v, off);
        if (lane == 0) atomicAdd(&g_acc, (double)v);
    }
}

__global__ void sg_final_kernel(float* __restrict__ out, long long n) {
    out[0] = (float)(-g_acc / (double)n);
}

extern "C" void kernel_launch(void* const* d_in, const int* in_sizes, int n_in,
                              void* d_out, int out_size) {
    const int*    tgt = (const int*)d_in[0];
    const int*    ctx = (const int*)d_in[1];
    const int*    neg = (const int*)d_in[2];
    const float4* Wh  = (const float4*)d_in[3];
    const float4* Wo  = (const float4*)d_in[4];
    float* out = (float*)d_out;

    const long long n = (long long)in_sizes[0];

    sg_init_kernel<<<1, 1>>>();
    sg_main_kernel<<<NBLOCKS, NTHREADS>>>(tgt, ctx, neg, Wh, Wo, n);
    sg_final_kernel<<<1, 1>>>(out, n);
}